// round 2
// baseline (speedup 1.0000x reference)
#include <cuda_runtime.h>

// out[b, q, j] = float( max(0, q - 127) + j )   for B=8, Q=4096, K=64.
//
// Derivation: the reference masks the local window [q-127, q] to +inf and
// future (k>q) to -inf before jax.lax.top_k(..., 64). top_k breaks ties
// lowest-index-first, so the top-64 are always the 64 smallest indices of
// the +inf window (padded by -inf ties ascending from q+1 when q < 63),
// i.e. max(0,q-127)+0..63. The input tensor I never affects the result.
//
// R1 post-mortem: rel_err was exactly 1.0 with int32 stores -> harness
// output buffer is float32 (int bit patterns read as denormals ~ 0).
// Store the indices as float32 values.

__global__ void TokenSelector_17755394801797_kernel(float4* __restrict__ out, int n_vec4) {
    int idx = blockIdx.x * blockDim.x + threadIdx.x;
    if (idx >= n_vec4) return;

    int lin = idx << 2;              // element index of first of 4 outputs
    int j   = lin & 63;              // within-row position (multiple of 4)
    int q   = (lin >> 6) & 4095;     // query row
    int start = q - 127;
    if (start < 0) start = 0;
    float base = (float)(start + j);

    float4 v;
    v.x = base;
    v.y = base + 1.0f;
    v.z = base + 2.0f;
    v.w = base + 3.0f;
    out[idx] = v;
}

extern "C" void kernel_launch(void* const* d_in, const int* in_sizes, int n_in,
                              void* d_out, int out_size) {
    (void)d_in; (void)in_sizes; (void)n_in;
    int n_vec4 = out_size >> 2;                  // 2,097,152 / 4 = 524,288
    int threads = 256;
    int blocks = (n_vec4 + threads - 1) / threads;
    TokenSelector_17755394801797_kernel<<<blocks, threads>>>((float4*)d_out, n_vec4);
}